// round 6
// baseline (speedup 1.0000x reference)
#include <cuda_runtime.h>
#include <cuda_bf16.h>
#include <math.h>

// Problem constants
#define B_      4
#define T_      2048
#define DIM_    2048
#define DIMV_   1024
#define INNER_  1024
#define HEADS_  16
#define DH_     64
#define NMEDIA_ 8
#define NVIS_   64
#define NKV_    512          // N_MEDIA * N_VIS keys per batch
#define LN_EPS_ 1e-5f

// Scratch (device globals: allocation-free per harness rules)
__device__ float g_yn  [(size_t)B_ * T_ * DIM_];      // 64 MB
__device__ float g_q   [(size_t)B_ * T_ * INNER_];    // 32 MB
__device__ float g_kv  [(size_t)B_ * NKV_ * 2 * INNER_]; // 16 MB
__device__ float g_attn[(size_t)B_ * T_ * INNER_];    // 32 MB
__device__ int   g_tt  [B_ * T_];

// ---------------------------------------------------------------------------
// LayerNorm: one block per row (2048 elems), 256 threads
// ---------------------------------------------------------------------------
__global__ __launch_bounds__(256) void ln_kernel(
    const float* __restrict__ y, const float* __restrict__ w,
    const float* __restrict__ bias, float* __restrict__ out)
{
    const int row = blockIdx.x;
    const float* x = y + (size_t)row * DIM_;
    float v[8];
    float s = 0.f, sq = 0.f;
#pragma unroll
    for (int i = 0; i < 8; i++) {
        float t = x[threadIdx.x + i * 256];
        v[i] = t; s += t; sq += t * t;
    }
#pragma unroll
    for (int o = 16; o > 0; o >>= 1) {
        s  += __shfl_xor_sync(0xffffffffu, s,  o);
        sq += __shfl_xor_sync(0xffffffffu, sq, o);
    }
    __shared__ float rs[8], rq[8];
    __shared__ float sh_mu, sh_rstd;
    const int wid = threadIdx.x >> 5, lane = threadIdx.x & 31;
    if (lane == 0) { rs[wid] = s; rq[wid] = sq; }
    __syncthreads();
    if (threadIdx.x == 0) {
        float S = 0.f, Q = 0.f;
#pragma unroll
        for (int i = 0; i < 8; i++) { S += rs[i]; Q += rq[i]; }
        float mu  = S * (1.f / DIM_);
        float var = Q * (1.f / DIM_) - mu * mu;
        sh_mu = mu;
        sh_rstd = rsqrtf(var + LN_EPS_);
    }
    __syncthreads();
    const float mu = sh_mu, rstd = sh_rstd;
    float* o = out + (size_t)row * DIM_;
#pragma unroll
    for (int i = 0; i < 8; i++) {
        int c = threadIdx.x + i * 256;
        o[c] = (v[i] - mu) * rstd * w[c] + bias[c];
    }
}

// ---------------------------------------------------------------------------
// text_time = inclusive cumsum of media_locations per batch row.
// One warp per batch row; lane handles 64 contiguous positions.
// ---------------------------------------------------------------------------
__global__ void tt_kernel(const int* __restrict__ loc, int* __restrict__ tt)
{
    const int w = threadIdx.x >> 5, lane = threadIdx.x & 31;
    if (w >= B_) return;
    const int* row = loc + w * T_;
    int cnt = 0;
#pragma unroll 8
    for (int i = 0; i < 64; i++) cnt += (row[lane * 64 + i] != 0);
    int incl = cnt;
#pragma unroll
    for (int o = 1; o < 32; o <<= 1) {
        int v = __shfl_up_sync(0xffffffffu, incl, o);
        if (lane >= o) incl += v;
    }
    int run = incl - cnt;
    for (int i = 0; i < 64; i++) {
        run += (row[lane * 64 + i] != 0);
        tt[w * T_ + lane * 64 + i] = run;
    }
}

// ---------------------------------------------------------------------------
// SGEMM: C[M,N] = alpha * A[M,K] @ B[K,N], row-major, fp32.
// 128x128 block tile, BK=8, 8x8 thread tile, 256 threads, double-buffered smem.
// Requires M%128==0, N%128==0, K%8==0 (true for all three calls).
// ---------------------------------------------------------------------------
__global__ __launch_bounds__(256) void sgemm128(
    const float* __restrict__ A, const float* __restrict__ B,
    float* __restrict__ C, int M, int N, int K, float alpha)
{
    __shared__ float As[2][8][128];
    __shared__ float Bs[2][8][128];

    const int tid  = threadIdx.x;
    const int aRow = tid >> 1;            // 0..127
    const int aCol = (tid & 1) << 2;      // 0 or 4
    const int bRow = tid >> 5;            // 0..7
    const int bCol = (tid & 31) << 2;     // 0..124
    const int trow = (tid >> 4) << 3;     // 0..120
    const int tcol = (tid & 15) << 3;     // 0..120

    const float* Ab = A + (size_t)blockIdx.y * 128 * K;
    const float* Bb = B + blockIdx.x * 128;

    float acc[8][8];
#pragma unroll
    for (int i = 0; i < 8; i++)
#pragma unroll
        for (int j = 0; j < 8; j++) acc[i][j] = 0.f;

    // preload tile 0
    {
        float4 a4 = *(const float4*)(Ab + (size_t)aRow * K + aCol);
        float4 b4 = *(const float4*)(Bb + (size_t)bRow * N + bCol);
        As[0][aCol + 0][aRow] = a4.x;
        As[0][aCol + 1][aRow] = a4.y;
        As[0][aCol + 2][aRow] = a4.z;
        As[0][aCol + 3][aRow] = a4.w;
        *(float4*)&Bs[0][bRow][bCol] = b4;
    }
    __syncthreads();

    int cur = 0;
    for (int k0 = 0; k0 < K; k0 += 8) {
        const int nk = k0 + 8;
        float4 a4n, b4n;
        if (nk < K) {
            a4n = *(const float4*)(Ab + (size_t)aRow * K + nk + aCol);
            b4n = *(const float4*)(Bb + (size_t)(nk + bRow) * N + bCol);
        }
#pragma unroll
        for (int k = 0; k < 8; k++) {
            float rm[8], rn[8];
            *(float4*)(rm)     = *(const float4*)&As[cur][k][trow];
            *(float4*)(rm + 4) = *(const float4*)&As[cur][k][trow + 4];
            *(float4*)(rn)     = *(const float4*)&Bs[cur][k][tcol];
            *(float4*)(rn + 4) = *(const float4*)&Bs[cur][k][tcol + 4];
#pragma unroll
            for (int i = 0; i < 8; i++)
#pragma unroll
                for (int j = 0; j < 8; j++)
                    acc[i][j] += rm[i] * rn[j];
        }
        if (nk < K) {
            const int nxt = cur ^ 1;
            As[nxt][aCol + 0][aRow] = a4n.x;
            As[nxt][aCol + 1][aRow] = a4n.y;
            As[nxt][aCol + 2][aRow] = a4n.z;
            As[nxt][aCol + 3][aRow] = a4n.w;
            *(float4*)&Bs[nxt][bRow][bCol] = b4n;
            __syncthreads();
            cur = nxt;
        }
    }

    float* Cb = C + (size_t)(blockIdx.y * 128) * N + blockIdx.x * 128;
#pragma unroll
    for (int i = 0; i < 8; i++) {
#pragma unroll
        for (int j = 0; j < 8; j += 4) {
            float4 o;
            o.x = alpha * acc[i][j + 0];
            o.y = alpha * acc[i][j + 1];
            o.z = alpha * acc[i][j + 2];
            o.w = alpha * acc[i][j + 3];
            *(float4*)(Cb + (size_t)(trow + i) * N + tcol + j) = o;
        }
    }
}

// ---------------------------------------------------------------------------
// Masked cross-attention. Block = (b, h, 256-query tile), 256 threads.
// Each query attends only the 64-key media chunk with media_time == text_time.
// K/V chunk staged in smem (padded to kill bank conflicts); warp per query.
// ---------------------------------------------------------------------------
__global__ __launch_bounds__(256) void attn_kernel(
    const float* __restrict__ q, const float* __restrict__ kv,
    const int* __restrict__ ttg, float* __restrict__ outp)
{
    __shared__ float ksm[64 * 65];
    __shared__ float vsm[64 * 65];
    __shared__ int needmask, anyfb;

    const int b = blockIdx.z, h = blockIdx.y, t0 = blockIdx.x * 256;
    const int tid = threadIdx.x, wid = tid >> 5, lane = tid & 31;

    if (tid == 0) { needmask = 0; anyfb = 0; }
    __syncthreads();
    {
        int tt = ttg[b * T_ + t0 + tid];
        if (tt >= 1 && tt <= NMEDIA_) atomicOr(&needmask, 1 << (tt - 1));
        else                          atomicExch(&anyfb, 1);
    }
    __syncthreads();
    const int nm = needmask, fb = anyfb;

    for (int m = 0; m < NMEDIA_; m++) {
        if (!((nm >> m) & 1)) continue;
        // stage K/V chunk [64 x 64] for (b, h, m)
        const size_t base = (size_t)(b * NKV_ + m * 64) * (2 * INNER_) + h * DH_;
#pragma unroll
        for (int r = 0; r < 16; r++) {
            int lin = tid + r * 256;
            int j = lin >> 6, d = lin & 63;
            ksm[j * 65 + d] = kv[base + (size_t)j * (2 * INNER_) + d];
            vsm[j * 65 + d] = kv[base + (size_t)j * (2 * INNER_) + INNER_ + d];
        }
        __syncthreads();

        for (int qi = 0; qi < 32; qi++) {
            const int t = t0 + wid * 32 + qi;
            if (ttg[b * T_ + t] != m + 1) continue;
            const float* qp = q + (size_t)(b * T_ + t) * INNER_ + h * DH_;
            const float q0 = qp[lane], q1 = qp[lane + 32];

            float s0 = 0.f, s1 = 0.f;
#pragma unroll
            for (int i = 0; i < 32; i++) {
                float qa = __shfl_sync(0xffffffffu, q0, i);
                float qb = __shfl_sync(0xffffffffu, q1, i);
                s0 += qa * ksm[lane * 65 + i]        + qb * ksm[lane * 65 + i + 32];
                s1 += qa * ksm[(lane + 32) * 65 + i] + qb * ksm[(lane + 32) * 65 + i + 32];
            }
            float mx = fmaxf(s0, s1);
#pragma unroll
            for (int o = 16; o > 0; o >>= 1)
                mx = fmaxf(mx, __shfl_xor_sync(0xffffffffu, mx, o));
            float e0 = __expf(s0 - mx), e1 = __expf(s1 - mx);
            float sum = e0 + e1;
#pragma unroll
            for (int o = 16; o > 0; o >>= 1)
                sum += __shfl_xor_sync(0xffffffffu, sum, o);
            const float inv = 1.f / sum;
            const float a0 = e0 * inv, a1 = e1 * inv;

            float o0 = 0.f, o1 = 0.f;
#pragma unroll
            for (int j = 0; j < 32; j++) {
                float aa = __shfl_sync(0xffffffffu, a0, j);
                float ab = __shfl_sync(0xffffffffu, a1, j);
                o0 += aa * vsm[j * 65 + lane]      + ab * vsm[(j + 32) * 65 + lane];
                o1 += aa * vsm[j * 65 + lane + 32] + ab * vsm[(j + 32) * 65 + lane + 32];
            }
            float* op = outp + (size_t)(b * T_ + t) * INNER_ + h * DH_;
            op[lane] = o0; op[lane + 32] = o1;
        }
        __syncthreads();
    }

    // Fallback for queries with no matching media (softmax over all-masked ->
    // uniform over all 512 keys). Never taken with the given mask, but correct.
    if (fb) {
        for (int qi = 0; qi < 32; qi++) {
            const int t = t0 + wid * 32 + qi;
            const int tt = ttg[b * T_ + t];
            if (tt >= 1 && tt <= NMEDIA_) continue;
            float o0 = 0.f, o1 = 0.f;
            for (int j = 0; j < NKV_; j++) {
                const float* vp = kv + (size_t)(b * NKV_ + j) * (2 * INNER_) + INNER_ + h * DH_;
                o0 += vp[lane]; o1 += vp[lane + 32];
            }
            const float invn = 1.f / (float)NKV_;
            float* op = outp + (size_t)(b * T_ + t) * INNER_ + h * DH_;
            op[lane] = o0 * invn; op[lane + 32] = o1 * invn;
        }
    }
}

// ---------------------------------------------------------------------------
// Launch: LN -> cumsum -> GEMM_Q -> GEMM_KV -> attention -> GEMM_Out
// ---------------------------------------------------------------------------
extern "C" void kernel_launch(void* const* d_in, const int* in_sizes, int n_in,
                              void* d_out, int out_size)
{
    const float* y     = (const float*)d_in[0];
    const float* media = (const float*)d_in[1];
    const int*   loc   = (const int*)  d_in[2];
    const float* lnw   = (const float*)d_in[3];
    const float* lnb   = (const float*)d_in[4];
    const float* Wq    = (const float*)d_in[5];
    const float* Wkv   = (const float*)d_in[6];
    const float* Wout  = (const float*)d_in[7];
    float* out = (float*)d_out;

    float *yn, *qb, *kvb, *attnb;
    int* ttb;
    cudaGetSymbolAddress((void**)&yn,    g_yn);
    cudaGetSymbolAddress((void**)&qb,    g_q);
    cudaGetSymbolAddress((void**)&kvb,   g_kv);
    cudaGetSymbolAddress((void**)&attnb, g_attn);
    cudaGetSymbolAddress((void**)&ttb,   g_tt);

    ln_kernel<<<B_ * T_, 256>>>(y, lnw, lnb, yn);
    tt_kernel<<<1, 128>>>(loc, ttb);

    // q = yn @ Wq * DIM_HEAD^-0.5   [8192x2048]@[2048x1024]
    sgemm128<<<dim3(INNER_ / 128, (B_ * T_) / 128), 256>>>(
        yn, Wq, qb, B_ * T_, INNER_, DIM_, 0.125f);

    // kv = media_f @ Wkv            [2048x1024]@[1024x2048]
    sgemm128<<<dim3((2 * INNER_) / 128, (B_ * NKV_) / 128), 256>>>(
        media, Wkv, kvb, B_ * NKV_, 2 * INNER_, DIMV_, 1.f);

    attn_kernel<<<dim3(T_ / 256, HEADS_, B_), 256>>>(qb, kvb, ttb, attnb);

    // out = attn @ Wout             [8192x1024]@[1024x2048]
    sgemm128<<<dim3(DIM_ / 128, (B_ * T_) / 128), 256>>>(
        attnb, Wout, out, B_ * T_, DIM_, INNER_, 1.f);
}

// round 9
// speedup vs baseline: 2.3455x; 2.3455x over previous
#include <cuda_runtime.h>
#include <cuda_bf16.h>
#include <math.h>
#include <stdint.h>

// Problem constants
#define B_      4
#define T_      2048
#define DIM_    2048
#define DIMV_   1024
#define INNER_  1024
#define HEADS_  16
#define DH_     64
#define NMEDIA_ 8
#define NVIS_   64
#define NKV_    512
#define LN_EPS_ 1e-5f

// ---------------------------------------------------------------------------
// Helpers (sm_80-era PTX only: ldmatrix / cp.async / mma.sync — no tcgen05;
// ptxas target is plain compute_103, arch-specific 'a' features unavailable)
// ---------------------------------------------------------------------------
__device__ __forceinline__ uint32_t smem_to_u32(const void* p) {
    uint32_t a;
    asm("{ .reg .u64 t; cvta.to.shared.u64 t, %1; cvt.u32.u64 %0, t; }" : "=r"(a) : "l"(p));
    return a;
}
#define CP_ASYNC16(sm, gp) \
    asm volatile("cp.async.cg.shared.global [%0], [%1], 16;" :: "r"(sm), "l"(gp))
#define CP_COMMIT() asm volatile("cp.async.commit_group;" ::: "memory")
#define CP_WAIT0()  asm volatile("cp.async.wait_group 0;" ::: "memory")
#define CP_WAIT1()  asm volatile("cp.async.wait_group 1;" ::: "memory")

__device__ __forceinline__ void ldsm4(uint32_t* r, uint32_t addr) {
    asm volatile("ldmatrix.sync.aligned.m8n8.x4.shared.b16 {%0,%1,%2,%3}, [%4];"
                 : "=r"(r[0]), "=r"(r[1]), "=r"(r[2]), "=r"(r[3]) : "r"(addr));
}
__device__ __forceinline__ void mma_bf16(float* d, const uint32_t* a, const uint32_t* b) {
    asm volatile(
        "mma.sync.aligned.m16n8k16.row.col.f32.bf16.bf16.f32 "
        "{%0,%1,%2,%3}, {%4,%5,%6,%7}, {%8,%9}, {%0,%1,%2,%3};"
        : "+f"(d[0]), "+f"(d[1]), "+f"(d[2]), "+f"(d[3])
        : "r"(a[0]), "r"(a[1]), "r"(a[2]), "r"(a[3]), "r"(b[0]), "r"(b[1]));
}
// SW64 swizzle on 64B rows: conflict-free ldmatrix + staging
static __device__ __forceinline__ uint32_t sw64(uint32_t off) {
    return off ^ ((off >> 3) & 0x30);
}

// ---------------------------------------------------------------------------
// Scratch (device globals: allocation-free)
// ---------------------------------------------------------------------------
__device__ __nv_bfloat16 g_ynh [(size_t)B_ * T_ * DIM_];
__device__ __nv_bfloat16 g_ynl [(size_t)B_ * T_ * DIM_];
__device__ __nv_bfloat16 g_medh[(size_t)B_ * NKV_ * DIMV_];
__device__ __nv_bfloat16 g_medl[(size_t)B_ * NKV_ * DIMV_];
__device__ __nv_bfloat16 g_WqTh[(size_t)INNER_ * DIM_];
__device__ __nv_bfloat16 g_WqTl[(size_t)INNER_ * DIM_];
__device__ __nv_bfloat16 g_WkvTh[(size_t)2 * INNER_ * DIMV_];
__device__ __nv_bfloat16 g_WkvTl[(size_t)2 * INNER_ * DIMV_];
__device__ __nv_bfloat16 g_WoTh[(size_t)DIM_ * INNER_];
__device__ __nv_bfloat16 g_WoTl[(size_t)DIM_ * INNER_];
__device__ float g_q   [(size_t)B_ * T_ * INNER_];
__device__ float g_kv  [(size_t)B_ * NKV_ * 2 * INNER_];
__device__ __nv_bfloat16 g_ath[(size_t)B_ * T_ * INNER_];
__device__ __nv_bfloat16 g_atl[(size_t)B_ * T_ * INNER_];
__device__ int   g_tt  [B_ * T_];

// ---------------------------------------------------------------------------
// LayerNorm -> hi/lo bf16 planes. One block per row, 256 threads.
// ---------------------------------------------------------------------------
__global__ __launch_bounds__(256) void ln_kernel(
    const float* __restrict__ y, const float* __restrict__ w,
    const float* __restrict__ bias,
    __nv_bfloat16* __restrict__ oh, __nv_bfloat16* __restrict__ ol)
{
    const int row = blockIdx.x;
    const float* x = y + (size_t)row * DIM_;
    float v[8];
    float s = 0.f, sq = 0.f;
#pragma unroll
    for (int i = 0; i < 8; i++) {
        float t = x[threadIdx.x + i * 256];
        v[i] = t; s += t; sq += t * t;
    }
#pragma unroll
    for (int o = 16; o > 0; o >>= 1) {
        s  += __shfl_xor_sync(0xffffffffu, s,  o);
        sq += __shfl_xor_sync(0xffffffffu, sq, o);
    }
    __shared__ float rs[8], rq[8];
    __shared__ float sh_mu, sh_rstd;
    const int wid = threadIdx.x >> 5, lane = threadIdx.x & 31;
    if (lane == 0) { rs[wid] = s; rq[wid] = sq; }
    __syncthreads();
    if (threadIdx.x == 0) {
        float S = 0.f, Q = 0.f;
#pragma unroll
        for (int i = 0; i < 8; i++) { S += rs[i]; Q += rq[i]; }
        float mu  = S * (1.f / DIM_);
        float var = Q * (1.f / DIM_) - mu * mu;
        sh_mu = mu; sh_rstd = rsqrtf(var + LN_EPS_);
    }
    __syncthreads();
    const float mu = sh_mu, rstd = sh_rstd;
#pragma unroll
    for (int i = 0; i < 8; i++) {
        int c = threadIdx.x + i * 256;
        float val = (v[i] - mu) * rstd * w[c] + bias[c];
        __nv_bfloat16 h = __float2bfloat16(val);
        oh[(size_t)row * DIM_ + c] = h;
        ol[(size_t)row * DIM_ + c] = __float2bfloat16(val - __bfloat162float(h));
    }
}

// ---------------------------------------------------------------------------
// text_time cumsum (one warp per batch row)
// ---------------------------------------------------------------------------
__global__ void tt_kernel(const int* __restrict__ loc, int* __restrict__ tt)
{
    const int w = threadIdx.x >> 5, lane = threadIdx.x & 31;
    if (w >= B_) return;
    const int* row = loc + w * T_;
    int cnt = 0;
#pragma unroll 8
    for (int i = 0; i < 64; i++) cnt += (row[lane * 64 + i] != 0);
    int incl = cnt;
#pragma unroll
    for (int o = 1; o < 32; o <<= 1) {
        int v = __shfl_up_sync(0xffffffffu, incl, o);
        if (lane >= o) incl += v;
    }
    int run = incl - cnt;
    for (int i = 0; i < 64; i++) {
        run += (row[lane * 64 + i] != 0);
        tt[w * T_ + lane * 64 + i] = run;
    }
}

// ---------------------------------------------------------------------------
// fp32 -> bf16 hi/lo split (elementwise)
// ---------------------------------------------------------------------------
__global__ void csplit(const float* __restrict__ x, __nv_bfloat16* __restrict__ h,
                       __nv_bfloat16* __restrict__ l, int n)
{
    int i = blockIdx.x * blockDim.x + threadIdx.x;
    if (i < n) {
        float v = x[i];
        __nv_bfloat16 hh = __float2bfloat16(v);
        h[i] = hh;
        l[i] = __float2bfloat16(v - __bfloat162float(hh));
    }
}

// ---------------------------------------------------------------------------
// Transpose + split: W[K,N] fp32 -> T{h,l}[N,K] bf16. block (32,8).
// ---------------------------------------------------------------------------
__global__ __launch_bounds__(256) void tsplit(
    const float* __restrict__ W, __nv_bfloat16* __restrict__ Th,
    __nv_bfloat16* __restrict__ Tl, int K, int N)
{
    __shared__ float t[32][33];
    const int n0 = blockIdx.x * 32, k0 = blockIdx.y * 32;
    const int tx = threadIdx.x, ty = threadIdx.y;
#pragma unroll
    for (int i = 0; i < 4; i++)
        t[ty + i * 8][tx] = W[(size_t)(k0 + ty + i * 8) * N + n0 + tx];
    __syncthreads();
#pragma unroll
    for (int i = 0; i < 4; i++) {
        float v = t[tx][ty + i * 8];
        __nv_bfloat16 h = __float2bfloat16(v);
        size_t o = (size_t)(n0 + ty + i * 8) * K + k0 + tx;
        Th[o] = h;
        Tl[o] = __float2bfloat16(v - __bfloat162float(h));
    }
}

// ---------------------------------------------------------------------------
// bf16x3 split GEMM via mma.sync: C[M,N] = alpha*(Ah+Al)[M,K] @ (Bh+Bl)[N,K]^T
// 128x128 CTA tile, BK=32, 8 warps (warp tile 32x64), cp.async double buffer,
// SW64-swizzled smem, conflict-free ldmatrix.
// ---------------------------------------------------------------------------
#define GBK   32
#define GPL   8192            // bytes per plane tile (128 rows x 64B)
#define GSTG  (4 * GPL)       // Ah, Al, Bh, Bl
#define GSMEM (2 * GSTG)      // 64 KB double-buffered

__global__ __launch_bounds__(256, 2) void gemm_ms(
    const __nv_bfloat16* __restrict__ Ah, const __nv_bfloat16* __restrict__ Al,
    const __nv_bfloat16* __restrict__ Bh, const __nv_bfloat16* __restrict__ Bl,
    float* __restrict__ C, int M, int N, int K, float alpha)
{
    extern __shared__ char dsm[];
    const uint32_t smU = smem_to_u32(dsm);

    const int tid = threadIdx.x;
    const int wid = tid >> 5, lane = tid & 31;
    const int wm = wid >> 1, wn = wid & 1;          // warp grid 4x2
    const int row0 = blockIdx.y * 128, col0 = blockIdx.x * 128;

    const __nv_bfloat16* plane[4] = { Ah, Al, Bh, Bl };
    const int prow[4] = { row0, row0, col0, col0 };

    // staging coords for this thread (2 iters x 4 planes, 16B each)
    const int sr = tid >> 2;          // 0..63  (row for iter 0; +64 for iter 1)
    const int sc = tid & 3;           // 16B column 0..3

    // stage chunk 0
    {
        const uint32_t st = smU;
#pragma unroll
        for (int p = 0; p < 4; p++) {
#pragma unroll
            for (int it = 0; it < 2; it++) {
                int r = sr + it * 64;
                uint32_t so = st + p * GPL + sw64((uint32_t)(r * 64 + sc * 16));
                const __nv_bfloat16* gp = plane[p] + (size_t)(prow[p] + r) * K + sc * 8;
                CP_ASYNC16(so, gp);
            }
        }
    }
    CP_COMMIT();

    float acc[2][8][4];
#pragma unroll
    for (int mi = 0; mi < 2; mi++)
#pragma unroll
        for (int g = 0; g < 8; g++)
#pragma unroll
            for (int j = 0; j < 4; j++) acc[mi][g][j] = 0.f;

    const int nC = K / GBK;
    int cur = 0;
    for (int c = 0; c < nC; c++) {
        if (c + 1 < nC) {
            const uint32_t st = smU + (cur ^ 1) * GSTG;
            const int k0 = (c + 1) * GBK;
#pragma unroll
            for (int p = 0; p < 4; p++) {
#pragma unroll
                for (int it = 0; it < 2; it++) {
                    int r = sr + it * 64;
                    uint32_t so = st + p * GPL + sw64((uint32_t)(r * 64 + sc * 16));
                    const __nv_bfloat16* gp = plane[p] + (size_t)(prow[p] + r) * K + k0 + sc * 8;
                    CP_ASYNC16(so, gp);
                }
            }
            CP_COMMIT();
            CP_WAIT1();
        } else {
            CP_WAIT0();
        }
        __syncthreads();

        const uint32_t st = smU + cur * GSTG;
#pragma unroll
        for (int s = 0; s < 2; s++) {
            // A fragments (hi & lo), 2 m16 tiles each
            uint32_t ah[2][4], al[2][4];
#pragma unroll
            for (int mi = 0; mi < 2; mi++) {
                int ar  = wm * 32 + mi * 16 + (lane & 15);
                int ac  = s * 2 + (lane >> 4);
                uint32_t off = sw64((uint32_t)(ar * 64 + ac * 16));
                ldsm4(ah[mi], st + off);              // Ah plane at 0
                ldsm4(al[mi], st + GPL + off);        // Al plane
            }
            // B fragments: 4 x (n16 x k16) per plane
#pragma unroll
            for (int nb = 0; nb < 4; nb++) {
                int br = wn * 64 + nb * 16 + ((lane >> 4) << 3) + (lane & 7);
                int bc = s * 2 + ((lane >> 3) & 1);
                uint32_t off = sw64((uint32_t)(br * 64 + bc * 16));
                uint32_t bh[4], bl[4];
                ldsm4(bh, st + 2 * GPL + off);
                ldsm4(bl, st + 3 * GPL + off);
#pragma unroll
                for (int mi = 0; mi < 2; mi++) {
#pragma unroll
                    for (int g = 0; g < 2; g++) {
                        float* d = acc[mi][nb * 2 + g];
                        mma_bf16(d, ah[mi], &bh[g * 2]);
                        mma_bf16(d, ah[mi], &bl[g * 2]);
                        mma_bf16(d, al[mi], &bh[g * 2]);
                    }
                }
            }
        }
        __syncthreads();
        cur ^= 1;
    }

    // epilogue: canonical m16n8 accumulator mapping
    const int er = row0 + wm * 32 + (lane >> 2);
    const int ec = col0 + wn * 64 + (lane & 3) * 2;
#pragma unroll
    for (int mi = 0; mi < 2; mi++) {
#pragma unroll
        for (int g = 0; g < 8; g++) {
            float* d = acc[mi][g];
            float2 v0 = { alpha * d[0], alpha * d[1] };
            float2 v1 = { alpha * d[2], alpha * d[3] };
            size_t base = (size_t)(er + mi * 16) * N + ec + g * 8;
            *(float2*)(C + base)                 = v0;
            *(float2*)(C + base + (size_t)8 * N) = v1;
        }
    }
}

// ---------------------------------------------------------------------------
// Masked cross-attention (fp32 in, bf16 hi/lo planes out).
// ---------------------------------------------------------------------------
__global__ __launch_bounds__(256) void attn_kernel(
    const float* __restrict__ q, const float* __restrict__ kv,
    const int* __restrict__ ttg,
    __nv_bfloat16* __restrict__ oph, __nv_bfloat16* __restrict__ opl)
{
    __shared__ float ksm[64 * 65];
    __shared__ float vsm[64 * 65];
    __shared__ int needmask, anyfb;

    const int b = blockIdx.z, h = blockIdx.y, t0 = blockIdx.x * 256;
    const int tid = threadIdx.x, wid = tid >> 5, lane = tid & 31;

    if (tid == 0) { needmask = 0; anyfb = 0; }
    __syncthreads();
    {
        int tt = ttg[b * T_ + t0 + tid];
        if (tt >= 1 && tt <= NMEDIA_) atomicOr(&needmask, 1 << (tt - 1));
        else                          atomicExch(&anyfb, 1);
    }
    __syncthreads();
    const int nm = needmask, fb = anyfb;

    for (int m = 0; m < NMEDIA_; m++) {
        if (!((nm >> m) & 1)) continue;
        const size_t base = (size_t)(b * NKV_ + m * 64) * (2 * INNER_) + h * DH_;
#pragma unroll
        for (int r = 0; r < 16; r++) {
            int lin = tid + r * 256;
            int j = lin >> 6, d = lin & 63;
            ksm[j * 65 + d] = kv[base + (size_t)j * (2 * INNER_) + d];
            vsm[j * 65 + d] = kv[base + (size_t)j * (2 * INNER_) + INNER_ + d];
        }
        __syncthreads();

        for (int qi = 0; qi < 32; qi++) {
            const int t = t0 + wid * 32 + qi;
            if (ttg[b * T_ + t] != m + 1) continue;
            const float* qp = q + (size_t)(b * T_ + t) * INNER_ + h * DH_;
            const float q0 = qp[lane], q1 = qp[lane + 32];

            float s0 = 0.f, s1 = 0.f;
#pragma unroll
            for (int i = 0; i < 32; i++) {
                float qa = __shfl_sync(0xffffffffu, q0, i);
                float qb = __shfl_sync(0xffffffffu, q1, i);
                s0 += qa * ksm[lane * 65 + i]        + qb * ksm[lane * 65 + i + 32];
                s1 += qa * ksm[(lane + 32) * 65 + i] + qb * ksm[(lane + 32) * 65 + i + 32];
            }
            float mx = fmaxf(s0, s1);
#pragma unroll
            for (int o = 16; o > 0; o >>= 1)
                mx = fmaxf(mx, __shfl_xor_sync(0xffffffffu, mx, o));
            float e0 = __expf(s0 - mx), e1 = __expf(s1 - mx);
            float sum = e0 + e1;
#pragma unroll
            for (int o = 16; o > 0; o >>= 1)
                sum += __shfl_xor_sync(0xffffffffu, sum, o);
            const float inv = 1.f / sum;
            const float a0 = e0 * inv, a1 = e1 * inv;

            float o0 = 0.f, o1 = 0.f;
#pragma unroll
            for (int j = 0; j < 32; j++) {
                float aa = __shfl_sync(0xffffffffu, a0, j);
                float ab = __shfl_sync(0xffffffffu, a1, j);
                o0 += aa * vsm[j * 65 + lane]      + ab * vsm[(j + 32) * 65 + lane];
                o1 += aa * vsm[j * 65 + lane + 32] + ab * vsm[(j + 32) * 65 + lane + 32];
            }
            const size_t ob = (size_t)(b * T_ + t) * INNER_ + h * DH_;
            __nv_bfloat16 h0 = __float2bfloat16(o0);
            __nv_bfloat16 h1 = __float2bfloat16(o1);
            oph[ob + lane]      = h0;
            oph[ob + lane + 32] = h1;
            opl[ob + lane]      = __float2bfloat16(o0 - __bfloat162float(h0));
            opl[ob + lane + 32] = __float2bfloat16(o1 - __bfloat162float(h1));
        }
        __syncthreads();
    }

    if (fb) {
        for (int qi = 0; qi < 32; qi++) {
            const int t = t0 + wid * 32 + qi;
            const int tt = ttg[b * T_ + t];
            if (tt >= 1 && tt <= NMEDIA_) continue;
            float o0 = 0.f, o1 = 0.f;
            for (int j = 0; j < NKV_; j++) {
                const float* vp = kv + (size_t)(b * NKV_ + j) * (2 * INNER_) + INNER_ + h * DH_;
                o0 += vp[lane]; o1 += vp[lane + 32];
            }
            const float invn = 1.f / (float)NKV_;
            o0 *= invn; o1 *= invn;
            const size_t ob = (size_t)(b * T_ + t) * INNER_ + h * DH_;
            __nv_bfloat16 h0 = __float2bfloat16(o0);
            __nv_bfloat16 h1 = __float2bfloat16(o1);
            oph[ob + lane]      = h0;
            oph[ob + lane + 32] = h1;
            opl[ob + lane]      = __float2bfloat16(o0 - __bfloat162float(h0));
            opl[ob + lane + 32] = __float2bfloat16(o1 - __bfloat162float(h1));
        }
    }
}

// ---------------------------------------------------------------------------
// Launch
// ---------------------------------------------------------------------------
extern "C" void kernel_launch(void* const* d_in, const int* in_sizes, int n_in,
                              void* d_out, int out_size)
{
    const float* y     = (const float*)d_in[0];
    const float* media = (const float*)d_in[1];
    const int*   loc   = (const int*)  d_in[2];
    const float* lnw   = (const float*)d_in[3];
    const float* lnb   = (const float*)d_in[4];
    const float* Wq    = (const float*)d_in[5];
    const float* Wkv   = (const float*)d_in[6];
    const float* Wout  = (const float*)d_in[7];
    float* out = (float*)d_out;

    __nv_bfloat16 *ynh, *ynl, *medh, *medl, *WqTh, *WqTl, *WkvTh, *WkvTl, *WoTh, *WoTl, *ath, *atl;
    float *qb, *kvb;
    int* ttb;
    cudaGetSymbolAddress((void**)&ynh,  g_ynh);
    cudaGetSymbolAddress((void**)&ynl,  g_ynl);
    cudaGetSymbolAddress((void**)&medh, g_medh);
    cudaGetSymbolAddress((void**)&medl, g_medl);
    cudaGetSymbolAddress((void**)&WqTh, g_WqTh);
    cudaGetSymbolAddress((void**)&WqTl, g_WqTl);
    cudaGetSymbolAddress((void**)&WkvTh, g_WkvTh);
    cudaGetSymbolAddress((void**)&WkvTl, g_WkvTl);
    cudaGetSymbolAddress((void**)&WoTh, g_WoTh);
    cudaGetSymbolAddress((void**)&WoTl, g_WoTl);
    cudaGetSymbolAddress((void**)&ath,  g_ath);
    cudaGetSymbolAddress((void**)&atl,  g_atl);
    cudaGetSymbolAddress((void**)&qb,   g_q);
    cudaGetSymbolAddress((void**)&kvb,  g_kv);
    cudaGetSymbolAddress((void**)&ttb,  g_tt);

    cudaFuncSetAttribute(gemm_ms, cudaFuncAttributeMaxDynamicSharedMemorySize, GSMEM);

    // prep: LN split, cumsum, weight transposes+splits, media split
    ln_kernel<<<B_ * T_, 256>>>(y, lnw, lnb, ynh, ynl);
    tt_kernel<<<1, 128>>>(loc, ttb);
    tsplit<<<dim3(INNER_ / 32, DIM_ / 32), dim3(32, 8)>>>(Wq, WqTh, WqTl, DIM_, INNER_);
    tsplit<<<dim3((2 * INNER_) / 32, DIMV_ / 32), dim3(32, 8)>>>(Wkv, WkvTh, WkvTl, DIMV_, 2 * INNER_);
    tsplit<<<dim3(DIM_ / 32, INNER_ / 32), dim3(32, 8)>>>(Wout, WoTh, WoTl, INNER_, DIM_);
    {
        int n = B_ * NKV_ * DIMV_;
        csplit<<<(n + 255) / 256, 256>>>(media, medh, medl, n);
    }

    // q = ln(y) @ Wq * scale   : M=8192, N=1024, K=2048
    gemm_ms<<<dim3(INNER_ / 128, (B_ * T_) / 128), 256, GSMEM>>>(
        ynh, ynl, WqTh, WqTl, qb, B_ * T_, INNER_, DIM_, 0.125f);

    // kv = media @ Wkv         : M=2048, N=2048, K=1024
    gemm_ms<<<dim3((2 * INNER_) / 128, (B_ * NKV_) / 128), 256, GSMEM>>>(
        medh, medl, WkvTh, WkvTl, kvb, B_ * NKV_, 2 * INNER_, DIMV_, 1.f);

    attn_kernel<<<dim3(T_ / 256, HEADS_, B_), 256>>>(qb, kvb, ttb, ath, atl);

    // out = attn @ Wout        : M=8192, N=2048, K=1024
    gemm_ms<<<dim3(DIM_ / 128, (B_ * T_) / 128), 256, GSMEM>>>(
        ath, atl, WoTh, WoTl, out, B_ * T_, DIM_, INNER_, 1.f);
}

// round 11
// speedup vs baseline: 2.3847x; 1.0167x over previous
#include <cuda_runtime.h>
#include <cuda_bf16.h>
#include <math.h>
#include <stdint.h>

// Problem constants
#define B_      4
#define T_      2048
#define DIM_    2048
#define DIMV_   1024
#define INNER_  1024
#define HEADS_  16
#define DH_     64
#define NMEDIA_ 8
#define NVIS_   64
#define NKV_    512
#define LN_EPS_ 1e-5f

// ---------------------------------------------------------------------------
// Helpers (sm_80-era PTX only: ldmatrix / cp.async / mma.sync — no tcgen05;
// ptxas target is plain compute_103, arch-specific 'a' features unavailable)
// ---------------------------------------------------------------------------
__device__ __forceinline__ uint32_t smem_to_u32(const void* p) {
    uint32_t a;
    asm("{ .reg .u64 t; cvta.to.shared.u64 t, %1; cvt.u32.u64 %0, t; }" : "=r"(a) : "l"(p));
    return a;
}
#define CP_ASYNC16(sm, gp) \
    asm volatile("cp.async.cg.shared.global [%0], [%1], 16;" :: "r"(sm), "l"(gp))
#define CP_COMMIT() asm volatile("cp.async.commit_group;" ::: "memory")
#define CP_WAIT0()  asm volatile("cp.async.wait_group 0;" ::: "memory")
#define CP_WAIT1()  asm volatile("cp.async.wait_group 1;" ::: "memory")

__device__ __forceinline__ void ldsm4(uint32_t* r, uint32_t addr) {
    asm volatile("ldmatrix.sync.aligned.m8n8.x4.shared.b16 {%0,%1,%2,%3}, [%4];"
                 : "=r"(r[0]), "=r"(r[1]), "=r"(r[2]), "=r"(r[3]) : "r"(addr));
}
__device__ __forceinline__ void mma_bf16(float* d, const uint32_t* a, const uint32_t* b) {
    asm volatile(
        "mma.sync.aligned.m16n8k16.row.col.f32.bf16.bf16.f32 "
        "{%0,%1,%2,%3}, {%4,%5,%6,%7}, {%8,%9}, {%0,%1,%2,%3};"
        : "+f"(d[0]), "+f"(d[1]), "+f"(d[2]), "+f"(d[3])
        : "r"(a[0]), "r"(a[1]), "r"(a[2]), "r"(a[3]), "r"(b[0]), "r"(b[1]));
}
// SW64 swizzle on 64B rows: conflict-free ldmatrix + staging
static __device__ __forceinline__ uint32_t sw64(uint32_t off) {
    return off ^ ((off >> 3) & 0x30);
}

// ---------------------------------------------------------------------------
// Scratch (device globals: allocation-free)
// ---------------------------------------------------------------------------
__device__ __nv_bfloat16 g_ynh [(size_t)B_ * T_ * DIM_];
__device__ __nv_bfloat16 g_ynl [(size_t)B_ * T_ * DIM_];
__device__ __nv_bfloat16 g_medh[(size_t)B_ * NKV_ * DIMV_];
__device__ __nv_bfloat16 g_medl[(size_t)B_ * NKV_ * DIMV_];
__device__ __nv_bfloat16 g_WqTh[(size_t)INNER_ * DIM_];
__device__ __nv_bfloat16 g_WqTl[(size_t)INNER_ * DIM_];
__device__ __nv_bfloat16 g_WkvTh[(size_t)2 * INNER_ * DIMV_];
__device__ __nv_bfloat16 g_WkvTl[(size_t)2 * INNER_ * DIMV_];
__device__ __nv_bfloat16 g_WoTh[(size_t)DIM_ * INNER_];
__device__ __nv_bfloat16 g_WoTl[(size_t)DIM_ * INNER_];
__device__ float g_q   [(size_t)B_ * T_ * INNER_];
__device__ float g_kv  [(size_t)B_ * NKV_ * 2 * INNER_];
__device__ __nv_bfloat16 g_ath[(size_t)B_ * T_ * INNER_];
__device__ __nv_bfloat16 g_atl[(size_t)B_ * T_ * INNER_];
__device__ int   g_tt  [B_ * T_];

// ---------------------------------------------------------------------------
// LayerNorm -> hi/lo bf16 planes. One block per row, 256 threads.
// ---------------------------------------------------------------------------
__global__ __launch_bounds__(256) void ln_kernel(
    const float* __restrict__ y, const float* __restrict__ w,
    const float* __restrict__ bias,
    __nv_bfloat16* __restrict__ oh, __nv_bfloat16* __restrict__ ol)
{
    const int row = blockIdx.x;
    const float* x = y + (size_t)row * DIM_;
    float v[8];
    float s = 0.f, sq = 0.f;
#pragma unroll
    for (int i = 0; i < 8; i++) {
        float t = x[threadIdx.x + i * 256];
        v[i] = t; s += t; sq += t * t;
    }
#pragma unroll
    for (int o = 16; o > 0; o >>= 1) {
        s  += __shfl_xor_sync(0xffffffffu, s,  o);
        sq += __shfl_xor_sync(0xffffffffu, sq, o);
    }
    __shared__ float rs[8], rq[8];
    __shared__ float sh_mu, sh_rstd;
    const int wid = threadIdx.x >> 5, lane = threadIdx.x & 31;
    if (lane == 0) { rs[wid] = s; rq[wid] = sq; }
    __syncthreads();
    if (threadIdx.x == 0) {
        float S = 0.f, Q = 0.f;
#pragma unroll
        for (int i = 0; i < 8; i++) { S += rs[i]; Q += rq[i]; }
        float mu  = S * (1.f / DIM_);
        float var = Q * (1.f / DIM_) - mu * mu;
        sh_mu = mu; sh_rstd = rsqrtf(var + LN_EPS_);
    }
    __syncthreads();
    const float mu = sh_mu, rstd = sh_rstd;
#pragma unroll
    for (int i = 0; i < 8; i++) {
        int c = threadIdx.x + i * 256;
        float val = (v[i] - mu) * rstd * w[c] + bias[c];
        __nv_bfloat16 h = __float2bfloat16(val);
        oh[(size_t)row * DIM_ + c] = h;
        ol[(size_t)row * DIM_ + c] = __float2bfloat16(val - __bfloat162float(h));
    }
}

// ---------------------------------------------------------------------------
// text_time cumsum (one warp per batch row)
// ---------------------------------------------------------------------------
__global__ void tt_kernel(const int* __restrict__ loc, int* __restrict__ tt)
{
    const int w = threadIdx.x >> 5, lane = threadIdx.x & 31;
    if (w >= B_) return;
    const int* row = loc + w * T_;
    int cnt = 0;
#pragma unroll 8
    for (int i = 0; i < 64; i++) cnt += (row[lane * 64 + i] != 0);
    int incl = cnt;
#pragma unroll
    for (int o = 1; o < 32; o <<= 1) {
        int v = __shfl_up_sync(0xffffffffu, incl, o);
        if (lane >= o) incl += v;
    }
    int run = incl - cnt;
    for (int i = 0; i < 64; i++) {
        run += (row[lane * 64 + i] != 0);
        tt[w * T_ + lane * 64 + i] = run;
    }
}

// ---------------------------------------------------------------------------
// fp32 -> bf16 hi/lo split (elementwise)
// ---------------------------------------------------------------------------
__global__ void csplit(const float* __restrict__ x, __nv_bfloat16* __restrict__ h,
                       __nv_bfloat16* __restrict__ l, int n)
{
    int i = blockIdx.x * blockDim.x + threadIdx.x;
    if (i < n) {
        float v = x[i];
        __nv_bfloat16 hh = __float2bfloat16(v);
        h[i] = hh;
        l[i] = __float2bfloat16(v - __bfloat162float(hh));
    }
}

// ---------------------------------------------------------------------------
// Transpose + split: W[K,N] fp32 -> T{h,l}[N,K] bf16. block (32,8).
// ---------------------------------------------------------------------------
__global__ __launch_bounds__(256) void tsplit(
    const float* __restrict__ W, __nv_bfloat16* __restrict__ Th,
    __nv_bfloat16* __restrict__ Tl, int K, int N)
{
    __shared__ float t[32][33];
    const int n0 = blockIdx.x * 32, k0 = blockIdx.y * 32;
    const int tx = threadIdx.x, ty = threadIdx.y;
#pragma unroll
    for (int i = 0; i < 4; i++)
        t[ty + i * 8][tx] = W[(size_t)(k0 + ty + i * 8) * N + n0 + tx];
    __syncthreads();
#pragma unroll
    for (int i = 0; i < 4; i++) {
        float v = t[tx][ty + i * 8];
        __nv_bfloat16 h = __float2bfloat16(v);
        size_t o = (size_t)(n0 + ty + i * 8) * K + k0 + tx;
        Th[o] = h;
        Tl[o] = __float2bfloat16(v - __bfloat162float(h));
    }
}

// ---------------------------------------------------------------------------
// bf16x3 split GEMM via mma.sync: C[M,N] = alpha*(Ah+Al)[M,K] @ (Bh+Bl)[N,K]^T
// 128x128 CTA tile, BK=32, 8 warps (warp tile 32x64), 3-stage cp.async
// pipeline (one __syncthreads per chunk), SW64-swizzled smem, conflict-free
// ldmatrix. 96KB smem/CTA -> 2 CTAs/SM.
// ---------------------------------------------------------------------------
#define GBK     32
#define GPL     8192          // bytes per plane tile (128 rows x 64B)
#define GSTG    (4 * GPL)     // Ah, Al, Bh, Bl
#define GSTAGES 3
#define GSMEM   (GSTAGES * GSTG)   // 96 KB

__global__ __launch_bounds__(256, 2) void gemm_ms(
    const __nv_bfloat16* __restrict__ Ah, const __nv_bfloat16* __restrict__ Al,
    const __nv_bfloat16* __restrict__ Bh, const __nv_bfloat16* __restrict__ Bl,
    float* __restrict__ C, int M, int N, int K, float alpha)
{
    extern __shared__ char dsm[];
    const uint32_t smU = smem_to_u32(dsm);

    const int tid = threadIdx.x;
    const int wid = tid >> 5, lane = tid & 31;
    const int wm = wid >> 1, wn = wid & 1;          // warp grid 4x2
    const int row0 = blockIdx.y * 128, col0 = blockIdx.x * 128;

    const __nv_bfloat16* plane[4] = { Ah, Al, Bh, Bl };
    const int prow[4] = { row0, row0, col0, col0 };

    // staging coords for this thread (2 iters x 4 planes, 16B each)
    const int sr = tid >> 2;          // 0..63  (row for iter 0; +64 for iter 1)
    const int sc = tid & 3;           // 16B column 0..3

    // stage chunk `k0` into stage buffer at smem base `st`
    auto stage_chunk = [&](uint32_t st, int k0) {
#pragma unroll
        for (int p = 0; p < 4; p++) {
#pragma unroll
            for (int it = 0; it < 2; it++) {
                int r = sr + it * 64;
                uint32_t so = st + p * GPL + sw64((uint32_t)(r * 64 + sc * 16));
                const __nv_bfloat16* gp = plane[p] + (size_t)(prow[p] + r) * K + k0 + sc * 8;
                CP_ASYNC16(so, gp);
            }
        }
    };

    const int nC = K / GBK;           // >= 32 for all our shapes

    // prologue: stages 0 and 1 in flight
    stage_chunk(smU, 0);
    CP_COMMIT();
    stage_chunk(smU + GSTG, GBK);
    CP_COMMIT();

    float acc[2][8][4];
#pragma unroll
    for (int mi = 0; mi < 2; mi++)
#pragma unroll
        for (int g = 0; g < 8; g++)
#pragma unroll
            for (int j = 0; j < 4; j++) acc[mi][g][j] = 0.f;

    int bufC = 0;                     // buffer holding chunk c
    int bufS = 2;                     // buffer to stage chunk c+2 into
    for (int c = 0; c < nC; c++) {
        // chunk c's cp.async group complete (<=1 newer group may be pending)
        if (c + 1 < nC) CP_WAIT1(); else CP_WAIT0();
        __syncthreads();

        // issue next staging first so it overlaps the MMA body below;
        // bufS == buffer of chunk c-1, retired by the barrier above
        if (c + 2 < nC) {
            stage_chunk(smU + bufS * GSTG, (c + 2) * GBK);
            CP_COMMIT();
        }

        const uint32_t st = smU + bufC * GSTG;
#pragma unroll
        for (int s = 0; s < 2; s++) {
            // A fragments (hi & lo), 2 m16 tiles each
            uint32_t ahf[2][4], alf[2][4];
#pragma unroll
            for (int mi = 0; mi < 2; mi++) {
                int ar  = wm * 32 + mi * 16 + (lane & 15);
                int ac  = s * 2 + (lane >> 4);
                uint32_t off = sw64((uint32_t)(ar * 64 + ac * 16));
                ldsm4(ahf[mi], st + off);              // Ah plane at 0
                ldsm4(alf[mi], st + GPL + off);        // Al plane
            }
            // B fragments: 4 x (n16 x k16) per plane
#pragma unroll
            for (int nb = 0; nb < 4; nb++) {
                int br = wn * 64 + nb * 16 + ((lane >> 4) << 3) + (lane & 7);
                int bc = s * 2 + ((lane >> 3) & 1);
                uint32_t off = sw64((uint32_t)(br * 64 + bc * 16));
                uint32_t bh[4], bl[4];
                ldsm4(bh, st + 2 * GPL + off);
                ldsm4(bl, st + 3 * GPL + off);
#pragma unroll
                for (int mi = 0; mi < 2; mi++) {
#pragma unroll
                    for (int g = 0; g < 2; g++) {
                        float* d = acc[mi][nb * 2 + g];
                        mma_bf16(d, ahf[mi], &bh[g * 2]);
                        mma_bf16(d, ahf[mi], &bl[g * 2]);
                        mma_bf16(d, alf[mi], &bh[g * 2]);
                    }
                }
            }
        }
        bufC = (bufC == GSTAGES - 1) ? 0 : bufC + 1;
        bufS = (bufS == GSTAGES - 1) ? 0 : bufS + 1;
    }

    // epilogue: canonical m16n8 accumulator mapping
    const int er = row0 + wm * 32 + (lane >> 2);
    const int ec = col0 + wn * 64 + (lane & 3) * 2;
#pragma unroll
    for (int mi = 0; mi < 2; mi++) {
#pragma unroll
        for (int g = 0; g < 8; g++) {
            float* d = acc[mi][g];
            float2 v0 = { alpha * d[0], alpha * d[1] };
            float2 v1 = { alpha * d[2], alpha * d[3] };
            size_t base = (size_t)(er + mi * 16) * N + ec + g * 8;
            *(float2*)(C + base)                 = v0;
            *(float2*)(C + base + (size_t)8 * N) = v1;
        }
    }
}

// ---------------------------------------------------------------------------
// Masked cross-attention (fp32 in, bf16 hi/lo planes out).
// ---------------------------------------------------------------------------
__global__ __launch_bounds__(256) void attn_kernel(
    const float* __restrict__ q, const float* __restrict__ kv,
    const int* __restrict__ ttg,
    __nv_bfloat16* __restrict__ oph, __nv_bfloat16* __restrict__ opl)
{
    __shared__ float ksm[64 * 65];
    __shared__ float vsm[64 * 65];
    __shared__ int needmask, anyfb;

    const int b = blockIdx.z, h = blockIdx.y, t0 = blockIdx.x * 256;
    const int tid = threadIdx.x, wid = tid >> 5, lane = tid & 31;

    if (tid == 0) { needmask = 0; anyfb = 0; }
    __syncthreads();
    {
        int tt = ttg[b * T_ + t0 + tid];
        if (tt >= 1 && tt <= NMEDIA_) atomicOr(&needmask, 1 << (tt - 1));
        else                          atomicExch(&anyfb, 1);
    }
    __syncthreads();
    const int nm = needmask, fb = anyfb;

    for (int m = 0; m < NMEDIA_; m++) {
        if (!((nm >> m) & 1)) continue;
        const size_t base = (size_t)(b * NKV_ + m * 64) * (2 * INNER_) + h * DH_;
#pragma unroll
        for (int r = 0; r < 16; r++) {
            int lin = tid + r * 256;
            int j = lin >> 6, d = lin & 63;
            ksm[j * 65 + d] = kv[base + (size_t)j * (2 * INNER_) + d];
            vsm[j * 65 + d] = kv[base + (size_t)j * (2 * INNER_) + INNER_ + d];
        }
        __syncthreads();

        for (int qi = 0; qi < 32; qi++) {
            const int t = t0 + wid * 32 + qi;
            if (ttg[b * T_ + t] != m + 1) continue;
            const float* qp = q + (size_t)(b * T_ + t) * INNER_ + h * DH_;
            const float q0 = qp[lane], q1 = qp[lane + 32];

            float s0 = 0.f, s1 = 0.f;
#pragma unroll
            for (int i = 0; i < 32; i++) {
                float qa = __shfl_sync(0xffffffffu, q0, i);
                float qb = __shfl_sync(0xffffffffu, q1, i);
                s0 += qa * ksm[lane * 65 + i]        + qb * ksm[lane * 65 + i + 32];
                s1 += qa * ksm[(lane + 32) * 65 + i] + qb * ksm[(lane + 32) * 65 + i + 32];
            }
            float mx = fmaxf(s0, s1);
#pragma unroll
            for (int o = 16; o > 0; o >>= 1)
                mx = fmaxf(mx, __shfl_xor_sync(0xffffffffu, mx, o));
            float e0 = __expf(s0 - mx), e1 = __expf(s1 - mx);
            float sum = e0 + e1;
#pragma unroll
            for (int o = 16; o > 0; o >>= 1)
                sum += __shfl_xor_sync(0xffffffffu, sum, o);
            const float inv = 1.f / sum;
            const float a0 = e0 * inv, a1 = e1 * inv;

            float o0 = 0.f, o1 = 0.f;
#pragma unroll
            for (int j = 0; j < 32; j++) {
                float aa = __shfl_sync(0xffffffffu, a0, j);
                float ab = __shfl_sync(0xffffffffu, a1, j);
                o0 += aa * vsm[j * 65 + lane]      + ab * vsm[(j + 32) * 65 + lane];
                o1 += aa * vsm[j * 65 + lane + 32] + ab * vsm[(j + 32) * 65 + lane + 32];
            }
            const size_t ob = (size_t)(b * T_ + t) * INNER_ + h * DH_;
            __nv_bfloat16 h0 = __float2bfloat16(o0);
            __nv_bfloat16 h1 = __float2bfloat16(o1);
            oph[ob + lane]      = h0;
            oph[ob + lane + 32] = h1;
            opl[ob + lane]      = __float2bfloat16(o0 - __bfloat162float(h0));
            opl[ob + lane + 32] = __float2bfloat16(o1 - __bfloat162float(h1));
        }
        __syncthreads();
    }

    if (fb) {
        for (int qi = 0; qi < 32; qi++) {
            const int t = t0 + wid * 32 + qi;
            const int tt = ttg[b * T_ + t];
            if (tt >= 1 && tt <= NMEDIA_) continue;
            float o0 = 0.f, o1 = 0.f;
            for (int j = 0; j < NKV_; j++) {
                const float* vp = kv + (size_t)(b * NKV_ + j) * (2 * INNER_) + INNER_ + h * DH_;
                o0 += vp[lane]; o1 += vp[lane + 32];
            }
            const float invn = 1.f / (float)NKV_;
            o0 *= invn; o1 *= invn;
            const size_t ob = (size_t)(b * T_ + t) * INNER_ + h * DH_;
            __nv_bfloat16 h0 = __float2bfloat16(o0);
            __nv_bfloat16 h1 = __float2bfloat16(o1);
            oph[ob + lane]      = h0;
            oph[ob + lane + 32] = h1;
            opl[ob + lane]      = __float2bfloat16(o0 - __bfloat162float(h0));
            opl[ob + lane + 32] = __float2bfloat16(o1 - __bfloat162float(h1));
        }
    }
}

// ---------------------------------------------------------------------------
// Launch
// ---------------------------------------------------------------------------
extern "C" void kernel_launch(void* const* d_in, const int* in_sizes, int n_in,
                              void* d_out, int out_size)
{
    const float* y     = (const float*)d_in[0];
    const float* media = (const float*)d_in[1];
    const int*   loc   = (const int*)  d_in[2];
    const float* lnw   = (const float*)d_in[3];
    const float* lnb   = (const float*)d_in[4];
    const float* Wq    = (const float*)d_in[5];
    const float* Wkv   = (const float*)d_in[6];
    const float* Wout  = (const float*)d_in[7];
    float* out = (float*)d_out;

    __nv_bfloat16 *ynh, *ynl, *medh, *medl, *WqTh, *WqTl, *WkvTh, *WkvTl, *WoTh, *WoTl, *ath, *atl;
    float *qb, *kvb;
    int* ttb;
    cudaGetSymbolAddress((void**)&ynh,  g_ynh);
    cudaGetSymbolAddress((void**)&ynl,  g_ynl);
    cudaGetSymbolAddress((void**)&medh, g_medh);
    cudaGetSymbolAddress((void**)&medl, g_medl);
    cudaGetSymbolAddress((void**)&WqTh, g_WqTh);
    cudaGetSymbolAddress((void**)&WqTl, g_WqTl);
    cudaGetSymbolAddress((void**)&WkvTh, g_WkvTh);
    cudaGetSymbolAddress((void**)&WkvTl, g_WkvTl);
    cudaGetSymbolAddress((void**)&WoTh, g_WoTh);
    cudaGetSymbolAddress((void**)&WoTl, g_WoTl);
    cudaGetSymbolAddress((void**)&ath,  g_ath);
    cudaGetSymbolAddress((void**)&atl,  g_atl);
    cudaGetSymbolAddress((void**)&qb,   g_q);
    cudaGetSymbolAddress((void**)&kvb,  g_kv);
    cudaGetSymbolAddress((void**)&ttb,  g_tt);

    cudaFuncSetAttribute(gemm_ms, cudaFuncAttributeMaxDynamicSharedMemorySize, GSMEM);

    // prep: LN split, cumsum, weight transposes+splits, media split
    ln_kernel<<<B_ * T_, 256>>>(y, lnw, lnb, ynh, ynl);
    tt_kernel<<<1, 128>>>(loc, ttb);
    tsplit<<<dim3(INNER_ / 32, DIM_ / 32), dim3(32, 8)>>>(Wq, WqTh, WqTl, DIM_, INNER_);
    tsplit<<<dim3((2 * INNER_) / 32, DIMV_ / 32), dim3(32, 8)>>>(Wkv, WkvTh, WkvTl, DIMV_, 2 * INNER_);
    tsplit<<<dim3(DIM_ / 32, INNER_ / 32), dim3(32, 8)>>>(Wout, WoTh, WoTl, INNER_, DIM_);
    {
        int n = B_ * NKV_ * DIMV_;
        csplit<<<(n + 255) / 256, 256>>>(media, medh, medl, n);
    }

    // q = ln(y) @ Wq * scale   : M=8192, N=1024, K=2048
    gemm_ms<<<dim3(INNER_ / 128, (B_ * T_) / 128), 256, GSMEM>>>(
        ynh, ynl, WqTh, WqTl, qb, B_ * T_, INNER_, DIM_, 0.125f);

    // kv = media @ Wkv         : M=2048, N=2048, K=1024
    gemm_ms<<<dim3((2 * INNER_) / 128, (B_ * NKV_) / 128), 256, GSMEM>>>(
        medh, medl, WkvTh, WkvTl, kvb, B_ * NKV_, 2 * INNER_, DIMV_, 1.f);

    attn_kernel<<<dim3(T_ / 256, HEADS_, B_), 256>>>(qb, kvb, ttb, ath, atl);

    // out = attn @ Wout        : M=8192, N=2048, K=1024
    gemm_ms<<<dim3(DIM_ / 128, (B_ * T_) / 128), 256, GSMEM>>>(
        ath, atl, WoTh, WoTl, out, B_ * T_, DIM_, INNER_, 1.f);
}